// round 15
// baseline (speedup 1.0000x reference)
#include <cuda_runtime.h>
#include <cstdint>

// Problem constants
#define NROWS   22743
#define ROWB    340            // bytes per row (85 f32)
#define NB      64
#define NCELLS  7581           // 76^2 + 38^2 + 19^2
#define BLK     512
#define GX      ((NCELLS + BLK - 1) / BLK)   // 15
#define NBLOCKS (GX * NB)                     // 960

__device__ float4       g_part4[NBLOCKS];
__device__ unsigned int g_cnt = 0;

__device__ __forceinline__ float bce_sig(float z, float t) {
    return __logf(1.0f + __expf(-z)) + (1.0f - t) * z;
}
__device__ __forceinline__ float bce_raw(float p, float t) {
    float pc = fmaxf(p, 1e-12f);
    return -(t * __logf(pc) + (1.0f - t) * __logf(1.0f - pc));
}

__global__ void __launch_bounds__(BLK)
yolo_fused(const float* __restrict__ x, const float* __restrict__ tgt,
           float* __restrict__ out) {
    const int cell = blockIdx.x * BLK + threadIdx.x;
    const int b    = blockIdx.y;

    float s_n = 0.f, s_A = 0.f, s_C = 0.f, s_O = 0.f;

    if (cell < NCELLS) {
        float g, objw;
        float AW[3], AH[3];
        if (cell < 5776) {               // grid 76
            g = 76.f; objw = 1.0f / (64.f * 17328.f);
            AW[0]=1.25f;   AH[0]=1.625f;
            AW[1]=2.0f;    AH[1]=3.75f;
            AW[2]=4.125f;  AH[2]=2.875f;
        } else if (cell < 7220) {        // grid 38
            g = 38.f; objw = 1.0f / (64.f * 4332.f);
            AW[0]=1.875f;  AH[0]=3.8125f;
            AW[1]=3.875f;  AH[1]=2.8125f;
            AW[2]=3.6875f; AH[2]=7.4375f;
        } else {                         // grid 19
            g = 19.f; objw = 1.0f / (64.f * 1083.f);
            AW[0]=3.625f;    AH[0]=2.8125f;
            AW[1]=4.875f;    AH[1]=6.1875f;
            AW[2]=11.65625f; AH[2]=10.1875f;
        }

        const size_t row0 = (size_t)b * NROWS + (size_t)3 * cell;
        const char* tbase = (const char*)tgt;
        const char* xbase = (const char*)x;

        // ---- 12 independent scalar loads up-front.
        //      Target (3 requests per line) -> __ldcg: L2 evict-normal, so the
        //      line is fetched from DRAM once and the sibling requests hit L2.
        //      x4 (single request per line)  -> __ldcs: streaming, evict-first.
        size_t rb[3];
        float  t2v[3], t3v[3], t4v[3], x4v[3];
        #pragma unroll
        for (int k = 0; k < 3; k++) rb[k] = (row0 + k) * (size_t)ROWB;
        #pragma unroll
        for (int k = 0; k < 3; k++) {
            t2v[k] = __ldcg((const float*)(tbase + rb[k] + 8));
            t3v[k] = __ldcg((const float*)(tbase + rb[k] + 12));
            t4v[k] = __ldcg((const float*)(tbase + rb[k] + 16));
            x4v[k] = __ldcs((const float*)(xbase + rb[k] + 16));
        }

        // ---- IoU terms ----
        float inter[3], ue[3];
        #pragma unroll
        for (int k = 0; k < 3; k++) {
            float gw = t2v[k] * g, gh = t3v[k] * g;
            float in_ = fminf(gw, AW[k]) * fminf(gh, AH[k]);
            inter[k] = in_;
            ue[k]    = gw * gh + AW[k] * AH[k] - in_ + 1e-12f;
        }

        // argmax(iou) via cross-multiplication, first-wins ties
        int best = 0;
        if (inter[1] * ue[0] > inter[0] * ue[1]) best = 1;
        if (inter[2] * ue[best] > inter[best] * ue[2]) best = 2;

        #pragma unroll
        for (int k = 0; k < 3; k++) {
            float keep = ((inter[k] <= 0.7f * ue[k]) || (k == best)) ? 1.f : 0.f;
            float z  = x4v[k] * keep;
            float tt = t4v[k] * keep;
            s_O += (__logf(1.0f + __expf(-z)) + (1.0f - tt) * z) * objw;

            if (t4v[k] > 0.f) {                    // ~2% of rows
                s_n += 1.f;
                const float* trk = (const float*)(tbase + rb[k]);
                const float* xrk = (const float*)(xbase + rb[k]);
                float t0 = trk[0], t1 = trk[1];
                float x0 = xrk[0], x1 = xrk[1], x2 = xrk[2], x3 = xrk[3];
                s_A += bce_sig(x0, t0) + bce_sig(x1, t1);
                s_A += bce_raw(x2, t2v[k]) + bce_raw(x3, t3v[k]);
                s_C += bce_sig(x4v[k], 1.0f);
            }
        }
    }

    // ---- Deterministic fixed-order block tree ----
    __shared__ float sm[BLK * 4];
    sm[threadIdx.x]           = s_n;
    sm[threadIdx.x + BLK]     = s_A;
    sm[threadIdx.x + 2 * BLK] = s_C;
    sm[threadIdx.x + 3 * BLK] = s_O;
    __syncthreads();
    #pragma unroll
    for (int off = BLK / 2; off > 0; off >>= 1) {
        if (threadIdx.x < off) {
            sm[threadIdx.x]           += sm[threadIdx.x + off];
            sm[threadIdx.x + BLK]     += sm[threadIdx.x + BLK + off];
            sm[threadIdx.x + 2 * BLK] += sm[threadIdx.x + 2 * BLK + off];
            sm[threadIdx.x + 3 * BLK] += sm[threadIdx.x + 3 * BLK + off];
        }
        __syncthreads();
    }

    __shared__ int amLast;
    if (threadIdx.x == 0) {
        int bid = blockIdx.y * gridDim.x + blockIdx.x;
        g_part4[bid] = make_float4(sm[0], sm[BLK], sm[2 * BLK], sm[3 * BLK]);
        __threadfence();
        unsigned v = atomicAdd(&g_cnt, 1u);
        amLast = (v == NBLOCKS - 1);
    }
    __syncthreads();

    if (amLast) {
        __threadfence();
        __shared__ double dm[BLK * 4];
        double a0d = 0, a1d = 0, a2d = 0, a3d = 0;
        for (int i = threadIdx.x; i < NBLOCKS; i += BLK) {
            float4 p = __ldcg(&g_part4[i]);
            a0d += (double)p.x; a1d += (double)p.y;
            a2d += (double)p.z; a3d += (double)p.w;
        }
        dm[threadIdx.x]           = a0d;
        dm[threadIdx.x + BLK]     = a1d;
        dm[threadIdx.x + 2 * BLK] = a2d;
        dm[threadIdx.x + 3 * BLK] = a3d;
        __syncthreads();
        #pragma unroll
        for (int off = BLK / 2; off > 0; off >>= 1) {
            if (threadIdx.x < off) {
                dm[threadIdx.x]           += dm[threadIdx.x + off];
                dm[threadIdx.x + BLK]     += dm[threadIdx.x + BLK + off];
                dm[threadIdx.x + 2 * BLK] += dm[threadIdx.x + 2 * BLK + off];
                dm[threadIdx.x + 3 * BLK] += dm[threadIdx.x + 3 * BLK + off];
            }
            __syncthreads();
        }
        if (threadIdx.x == 0) {
            double n = dm[0];
            if (n < 1.0) n = 1.0;
            double r = dm[BLK] / (2.0 * n)
                     + dm[2 * BLK] / n
                     + dm[3 * BLK];
            out[0] = (float)r;
            g_cnt = 0;
        }
    }
}

extern "C" void kernel_launch(void* const* d_in, const int* in_sizes, int n_in,
                              void* d_out, int out_size) {
    const float* x   = (const float*)d_in[0];
    const float* tgt = (const float*)d_in[1];
    dim3 grid(GX, NB);
    yolo_fused<<<grid, BLK>>>(x, tgt, (float*)d_out);
}

// round 16
// speedup vs baseline: 1.0575x; 1.0575x over previous
#include <cuda_runtime.h>
#include <cstdint>

// Problem constants
#define NROWS   22743
#define ROWB    340            // bytes per row (85 f32)
#define NB      64
#define NCELLS  7581           // 76^2 + 38^2 + 19^2
#define BLK     512
#define GX      ((NCELLS + BLK - 1) / BLK)   // 15
#define NBLOCKS (GX * NB)                     // 960

__device__ float4       g_part4[NBLOCKS];
__device__ unsigned int g_cnt = 0;

__device__ __forceinline__ float bce_sig(float z, float t) {
    return __logf(1.0f + __expf(-z)) + (1.0f - t) * z;
}
__device__ __forceinline__ float bce_raw(float p, float t) {
    float pc = fmaxf(p, 1e-12f);
    return -(t * __logf(pc) + (1.0f - t) * __logf(1.0f - pc));
}

__global__ void __launch_bounds__(BLK)
yolo_fused(const float* __restrict__ x, const float* __restrict__ tgt,
           float* __restrict__ out) {
    const int cell = blockIdx.x * BLK + threadIdx.x;
    const int b    = blockIdx.y;

    float s_n = 0.f, s_A = 0.f, s_C = 0.f, s_O = 0.f;

    if (cell < NCELLS) {
        float g, objw;
        float AW[3], AH[3];
        if (cell < 5776) {               // grid 76
            g = 76.f; objw = 1.0f / (64.f * 17328.f);
            AW[0]=1.25f;   AH[0]=1.625f;
            AW[1]=2.0f;    AH[1]=3.75f;
            AW[2]=4.125f;  AH[2]=2.875f;
        } else if (cell < 7220) {        // grid 38
            g = 38.f; objw = 1.0f / (64.f * 4332.f);
            AW[0]=1.875f;  AH[0]=3.8125f;
            AW[1]=3.875f;  AH[1]=2.8125f;
            AW[2]=3.6875f; AH[2]=7.4375f;
        } else {                         // grid 19
            g = 19.f; objw = 1.0f / (64.f * 1083.f);
            AW[0]=3.625f;    AH[0]=2.8125f;
            AW[1]=4.875f;    AH[1]=6.1875f;
            AW[2]=11.65625f; AH[2]=10.1875f;
        }

        const size_t row0 = (size_t)b * NROWS + (size_t)3 * cell;
        const char* tbase = (const char*)tgt;
        const char* xbase = (const char*)x;

        // ---- 12 independent scalar loads up-front.
        //      Target (3 requests per line) -> __ldcg: L2 evict-normal, so the
        //      line is fetched from DRAM once and the sibling requests hit L2.
        //      x4 (single request per line)  -> __ldcs: streaming, evict-first.
        size_t rb[3];
        float  t2v[3], t3v[3], t4v[3], x4v[3];
        #pragma unroll
        for (int k = 0; k < 3; k++) rb[k] = (row0 + k) * (size_t)ROWB;
        #pragma unroll
        for (int k = 0; k < 3; k++) {
            t2v[k] = __ldcg((const float*)(tbase + rb[k] + 8));
            t3v[k] = __ldcg((const float*)(tbase + rb[k] + 12));
            t4v[k] = __ldcg((const float*)(tbase + rb[k] + 16));
            x4v[k] = __ldcs((const float*)(xbase + rb[k] + 16));
        }

        // ---- IoU terms ----
        float inter[3], ue[3];
        #pragma unroll
        for (int k = 0; k < 3; k++) {
            float gw = t2v[k] * g, gh = t3v[k] * g;
            float in_ = fminf(gw, AW[k]) * fminf(gh, AH[k]);
            inter[k] = in_;
            ue[k]    = gw * gh + AW[k] * AH[k] - in_ + 1e-12f;
        }

        // argmax(iou) via cross-multiplication, first-wins ties
        int best = 0;
        if (inter[1] * ue[0] > inter[0] * ue[1]) best = 1;
        if (inter[2] * ue[best] > inter[best] * ue[2]) best = 2;

        #pragma unroll
        for (int k = 0; k < 3; k++) {
            float keep = ((inter[k] <= 0.7f * ue[k]) || (k == best)) ? 1.f : 0.f;
            float z  = x4v[k] * keep;
            float tt = t4v[k] * keep;
            s_O += (__logf(1.0f + __expf(-z)) + (1.0f - tt) * z) * objw;

            if (t4v[k] > 0.f) {                    // ~2% of rows
                s_n += 1.f;
                const float* trk = (const float*)(tbase + rb[k]);
                const float* xrk = (const float*)(xbase + rb[k]);
                float t0 = trk[0], t1 = trk[1];
                float x0 = xrk[0], x1 = xrk[1], x2 = xrk[2], x3 = xrk[3];
                s_A += bce_sig(x0, t0) + bce_sig(x1, t1);
                s_A += bce_raw(x2, t2v[k]) + bce_raw(x3, t3v[k]);
                s_C += bce_sig(x4v[k], 1.0f);
            }
        }
    }

    // ---- Deterministic fixed-order block tree ----
    __shared__ float sm[BLK * 4];
    sm[threadIdx.x]           = s_n;
    sm[threadIdx.x + BLK]     = s_A;
    sm[threadIdx.x + 2 * BLK] = s_C;
    sm[threadIdx.x + 3 * BLK] = s_O;
    __syncthreads();
    #pragma unroll
    for (int off = BLK / 2; off > 0; off >>= 1) {
        if (threadIdx.x < off) {
            sm[threadIdx.x]           += sm[threadIdx.x + off];
            sm[threadIdx.x + BLK]     += sm[threadIdx.x + BLK + off];
            sm[threadIdx.x + 2 * BLK] += sm[threadIdx.x + 2 * BLK + off];
            sm[threadIdx.x + 3 * BLK] += sm[threadIdx.x + 3 * BLK + off];
        }
        __syncthreads();
    }

    __shared__ int amLast;
    if (threadIdx.x == 0) {
        int bid = blockIdx.y * gridDim.x + blockIdx.x;
        g_part4[bid] = make_float4(sm[0], sm[BLK], sm[2 * BLK], sm[3 * BLK]);
        __threadfence();
        unsigned v = atomicAdd(&g_cnt, 1u);
        amLast = (v == NBLOCKS - 1);
    }
    __syncthreads();

    if (amLast) {
        __threadfence();
        __shared__ double dm[BLK * 4];
        double a0d = 0, a1d = 0, a2d = 0, a3d = 0;
        for (int i = threadIdx.x; i < NBLOCKS; i += BLK) {
            float4 p = __ldcg(&g_part4[i]);
            a0d += (double)p.x; a1d += (double)p.y;
            a2d += (double)p.z; a3d += (double)p.w;
        }
        dm[threadIdx.x]           = a0d;
        dm[threadIdx.x + BLK]     = a1d;
        dm[threadIdx.x + 2 * BLK] = a2d;
        dm[threadIdx.x + 3 * BLK] = a3d;
        __syncthreads();
        #pragma unroll
        for (int off = BLK / 2; off > 0; off >>= 1) {
            if (threadIdx.x < off) {
                dm[threadIdx.x]           += dm[threadIdx.x + off];
                dm[threadIdx.x + BLK]     += dm[threadIdx.x + BLK + off];
                dm[threadIdx.x + 2 * BLK] += dm[threadIdx.x + 2 * BLK + off];
                dm[threadIdx.x + 3 * BLK] += dm[threadIdx.x + 3 * BLK + off];
            }
            __syncthreads();
        }
        if (threadIdx.x == 0) {
            double n = dm[0];
            if (n < 1.0) n = 1.0;
            double r = dm[BLK] / (2.0 * n)
                     + dm[2 * BLK] / n
                     + dm[3 * BLK];
            out[0] = (float)r;
            g_cnt = 0;
        }
    }
}

extern "C" void kernel_launch(void* const* d_in, const int* in_sizes, int n_in,
                              void* d_out, int out_size) {
    const float* x   = (const float*)d_in[0];
    const float* tgt = (const float*)d_in[1];
    dim3 grid(GX, NB);
    yolo_fused<<<grid, BLK>>>(x, tgt, (float*)d_out);
}